// round 9
// baseline (speedup 1.0000x reference)
#include <cuda_runtime.h>
#include <cstdint>

// ---------------------------------------------------------------------------
// MoE_72808285602017 — PropertyLossTracker fused segment reduction
//   inputs : property_ids (N int32), token_losses (N f32),
//            prop_freq (P f32), batch_counter (1 int32)
//   outputs: [stratified_loss, unweighted_loss, new_freq[P]]  (P+2 f32)
//
// R9: ONE kernel, two block roles. Blocks 0..147 = R7's proven segacc workers
//     (148x1024, 1 CTA/SM, fastest measured 23.0us). Blocks 148..151 = epilogue
//     blocks (4x1024 = 1 prop/thread) that co-reside, prefetch, nanosleep-poll
//     the worker ticket, then run the tail in-kernel. Removes the second graph
//     node whose fixed ~8us boundary cost dominated R5-R8.
// ---------------------------------------------------------------------------

#define NPROP 4096
#define WORKERS 148
#define EPI_CTAS 4
#define TOTAL_CTAS (WORKERS + EPI_CTAS)

// Local 32-bit cell: (count << 24) + round(loss * 2^16) via one FFMA+F2I
// per-worker tokens ~113k -> per-cell expected ~27.6 counts (cap 255), safe.
#define LSCALE 65536.0f
#define LBIAS  16777216.0f            // 2^24 == one local count unit
#define LCNT_SHIFT 24

// Global 64-bit cell: (count << 40) + sum_units16
#define GCNT_SHIFT 40
#define GINV_SCALE (1.0f / 65536.0f)
#define GONE (1ULL << GCNT_SHIFT)

#define SCALE32 4294967296.0          // 2^32 fixed point for scalar merge

__device__ unsigned long long g_acc[NPROP];   // zeroed at load; epi re-zeroes
__device__ unsigned long long g_scal[3];      // {mw, w, t_units16}; last epi resets
__device__ unsigned int       g_ticket;       // workers done counter
__device__ unsigned int       g_ticket2;      // epi blocks done counter

__global__ void __launch_bounds__(1024, 2)
fused_kernel(const int* __restrict__ ids,
             const float* __restrict__ losses,
             const float* __restrict__ prop_freq,
             const int* __restrict__ bc_ptr,
             float* __restrict__ out,
             long long n)
{
    const int bid = blockIdx.x;
    const int tid = threadIdx.x;

    if (bid < WORKERS) {
        // =================== WORKER ROLE (R7 segacc, proven) ===============
        __shared__ unsigned int s_acc[NPROP];
        #pragma unroll
        for (int i = tid; i < NPROP; i += 1024) s_acc[i] = 0u;
        __syncthreads();

        const long long n4 = n >> 2;                 // N is a multiple of 4
        const int4*   id4 = (const int4*)ids;
        const float4* ls4 = (const float4*)losses;
        const long long stride = (long long)WORKERS * 1024;

        long long i = (long long)bid * 1024 + tid;
        #pragma unroll 2
        for (; i < n4; i += stride) {
            int4   id = __ldcs(&id4[i]);             // streamed once
            float4 ls = __ldcs(&ls4[i]);
            atomicAdd(&s_acc[id.x], __float2uint_rn(fmaf(ls.x, LSCALE, LBIAS)));
            atomicAdd(&s_acc[id.y], __float2uint_rn(fmaf(ls.y, LSCALE, LBIAS)));
            atomicAdd(&s_acc[id.z], __float2uint_rn(fmaf(ls.z, LSCALE, LBIAS)));
            atomicAdd(&s_acc[id.w], __float2uint_rn(fmaf(ls.w, LSCALE, LBIAS)));
        }
        // scalar tail (defensive; N % 4 == 0 here)
        for (long long t = (n4 << 2) + (long long)bid * 1024 + tid;
             t < n; t += stride) {
            atomicAdd(&s_acc[ids[t]], __float2uint_rn(fmaf(losses[t], LSCALE, LBIAS)));
        }
        __syncthreads();

        // flush block partials to global (repacked to 64-bit layout)
        #pragma unroll
        for (int k = tid; k < NPROP; k += 1024) {
            unsigned int v = s_acc[k];
            if (v) {
                unsigned long long g =
                    ((unsigned long long)(v >> LCNT_SHIFT) << GCNT_SHIFT)
                    + (unsigned long long)(v & 0x00FFFFFFu);
                atomicAdd(&g_acc[k], g);
            }
        }
        // release: make flush visible, then signal
        __threadfence();
        __syncthreads();
        if (tid == 0) atomicAdd(&g_ticket, 1u);
        return;
    }

    // ====================== EPILOGUE ROLE ==================================
    const int k = (bid - WORKERS) * 1024 + tid;     // 0..4095, 1 prop/thread

    // prefetch everything independent of the workers
    const float pf = __ldg(&prop_freq[k]);
    const float bc = (float)__ldg(bc_ptr);
    const float n_tokens = (float)n;

    const float EMA_DECAY = 0.99f;
    const float ONE_MINUS = 1.0f - 0.99f;
    const float MIN_FREQ  = 1e-5f;
    const float MAX_W     = 30.0f;
    const float WARMUP    = 1000.0f;
    const float SLOW      = 3000.0f;
    const float RAMPB     = 200.0f;

    const float ramp = fminf(1.0f, (bc - WARMUP) / RAMPB);
    const float frac = bc / SLOW;
    const bool  slow_blend = (bc <= SLOW);
    const bool  in_warmup  = (bc <= WARMUP);

    // park the block; thread 0 polls the worker ticket with sleep backoff
    if (tid == 0) {
        while (atomicAdd(&g_ticket, 0u) < (unsigned)WORKERS) __nanosleep(256);
    }
    __syncthreads();
    __threadfence();    // acquire: all workers' g_acc atomics visible

    unsigned long long v = __ldcg(&g_acc[k]);
    g_acc[k] = 0ULL;                                // reset scratch for next replay

    float cnt = (float)(v >> GCNT_SHIFT);
    unsigned long long units = v & (GONE - 1ULL);
    float sum = (float)units * GINV_SCALE;
    bool present = cnt > 0.0f;

    float mean = present ? (sum / fmaxf(cnt, 1.0f)) : 0.0f;

    // EMA frequency update
    float bfreq = cnt / (n_tokens + 1e-6f);
    float nf = pf * EMA_DECAY + (present ? ONE_MINUS * bfreq : 0.0f);
    out[2 + k] = nf;

    // inverse-frequency weight with warmup/ramp branches
    float fc  = fmaxf(nf, MIN_FREQ);
    float raw = rsqrtf(fc + 1e-6f);                 // 1/f^0.5
    raw = 1.0f + ramp * (raw - 1.0f);
    raw = fminf(MAX_W, raw);
    if (slow_blend) raw = raw * frac + (1.0f - frac);
    if (in_warmup)  raw = 1.0f;

    float w  = present ? raw : 0.0f;
    float mw = mean * w;

    // block tree reduction (1024 threads = 32 warps), fixed order = deterministic
    const unsigned FULL = 0xFFFFFFFFu;
    unsigned long long tu = units;
    #pragma unroll
    for (int off = 16; off > 0; off >>= 1) {
        mw += __shfl_down_sync(FULL, mw, off);
        w  += __shfl_down_sync(FULL, w,  off);
        tu += __shfl_down_sync(FULL, tu, off);
    }
    __shared__ float s_mw[32], s_w[32];
    __shared__ unsigned long long s_tu[32];
    int lane = tid & 31, warp = tid >> 5;
    if (lane == 0) { s_mw[warp] = mw; s_w[warp] = w; s_tu[warp] = tu; }
    __syncthreads();
    if (tid == 0) {
        float bmw = 0.0f, bw = 0.0f;
        unsigned long long btu = 0ULL;
        #pragma unroll
        for (int j = 0; j < 32; j++) { bmw += s_mw[j]; bw += s_w[j]; btu += s_tu[j]; }
        // integer fixed-point atomics: exact + order-independent = deterministic
        atomicAdd(&g_scal[0], (unsigned long long)llrint((double)bmw * SCALE32));
        atomicAdd(&g_scal[1], (unsigned long long)llrint((double)bw  * SCALE32));
        atomicAdd(&g_scal[2], btu);
        __threadfence();
        if (atomicAdd(&g_ticket2, 1u) == (unsigned)(EPI_CTAS - 1)) {
            __threadfence();   // acquire all epi blocks' g_scal contributions
            double dmw = (double)__ldcg(&g_scal[0]) / SCALE32;
            double dw  = (double)__ldcg(&g_scal[1]) / SCALE32;
            double dt  = (double)__ldcg(&g_scal[2]) * (1.0 / 65536.0);
            out[0] = (float)(dmw / (dw + 1e-6));        // stratified loss
            out[1] = (float)(dt / (double)n_tokens);    // unweighted mean loss
            g_scal[0] = 0ULL; g_scal[1] = 0ULL; g_scal[2] = 0ULL;
            g_ticket  = 0u;                             // reset for next replay
            g_ticket2 = 0u;
        }
    }
}

// ---------------------------------------------------------------------------
extern "C" void kernel_launch(void* const* d_in, const int* in_sizes, int n_in,
                              void* d_out, int out_size)
{
    const int*   ids    = (const int*)d_in[0];
    const float* losses = (const float*)d_in[1];
    const float* freq   = (const float*)d_in[2];
    const int*   bc     = (const int*)d_in[3];
    long long n = (long long)in_sizes[0];
    float* out = (float*)d_out;

    fused_kernel<<<TOTAL_CTAS, 1024>>>(ids, losses, freq, bc, out, n);
}

// round 10
// speedup vs baseline: 1.0580x; 1.0580x over previous
#include <cuda_runtime.h>
#include <cstdint>

// ---------------------------------------------------------------------------
// MoE_72808285602017 — PropertyLossTracker fused segment reduction
//   inputs : property_ids (N int32), token_losses (N f32),
//            prop_freq (P f32), batch_counter (1 int32)
//   outputs: [stratified_loss, unweighted_loss, new_freq[P]]  (P+2 f32)
//
// R10: R7 config (148x1024 workers @ 1 CTA/SM, plain loads, PDL epi 8x512)
//      with the PDL trigger moved to the FIRST instruction of each worker.
//      Previously the trigger sat after the flush, so the epilogue could never
//      launch/prefetch/park during the mainloop. Now it can: epi blocks
//      co-reside in the free 1024-thread slot, prefetch, and park in
//      cudaGridDependencySynchronize (which still guarantees full primary
//      completion + memory visibility before g_acc is read).
// ---------------------------------------------------------------------------

#define NPROP 4096
#define NBLOCKS 148

// Local 32-bit cell: (count << 24) + round(loss * 2^16) via one FFMA+F2I
// per-block tokens ~113k -> per-cell expected ~27.6 counts (cap 255), safe.
#define LSCALE 65536.0f
#define LBIAS  16777216.0f            // 2^24 == one local count unit
#define LCNT_SHIFT 24

// Global 64-bit cell: (count << 40) + sum_units16
#define GCNT_SHIFT 40
#define GINV_SCALE (1.0f / 65536.0f)
#define GONE (1ULL << GCNT_SHIFT)

#define SCALE32 4294967296.0          // 2^32 fixed point for scalar merge

__device__ unsigned long long g_acc[NPROP];   // zeroed at load; epilogue re-zeroes
__device__ unsigned long long g_scal[3];      // {mw, w, t_units16}; last block resets
__device__ unsigned int       g_ticket;       // epilogue block ticket

// --- Kernel 1: token accumulation (R7 core, trigger moved to entry) ----------
__global__ void __launch_bounds__(1024, 1)
segacc_kernel(const int* __restrict__ ids,
              const float* __restrict__ losses,
              long long n)
{
    // PDL: allow the dependent epilogue grid to launch IMMEDIATELY so its
    // blocks co-reside, prefetch, and park during our mainloop. Memory
    // visibility for it is still gated by cudaGridDependencySynchronize.
    cudaTriggerProgrammaticLaunchCompletion();

    __shared__ unsigned int s_acc[NPROP];
    #pragma unroll
    for (int i = threadIdx.x; i < NPROP; i += 1024) s_acc[i] = 0u;
    __syncthreads();

    const long long n4 = n >> 2;                 // N is a multiple of 4
    const int4*   id4 = (const int4*)ids;
    const float4* ls4 = (const float4*)losses;
    const long long stride = (long long)gridDim.x * 1024;

    long long i = (long long)blockIdx.x * 1024 + threadIdx.x;
    #pragma unroll 2
    for (; i < n4; i += stride) {
        int4   id = id4[i];
        float4 ls = ls4[i];
        atomicAdd(&s_acc[id.x], __float2uint_rn(fmaf(ls.x, LSCALE, LBIAS)));
        atomicAdd(&s_acc[id.y], __float2uint_rn(fmaf(ls.y, LSCALE, LBIAS)));
        atomicAdd(&s_acc[id.z], __float2uint_rn(fmaf(ls.z, LSCALE, LBIAS)));
        atomicAdd(&s_acc[id.w], __float2uint_rn(fmaf(ls.w, LSCALE, LBIAS)));
    }
    // scalar tail (defensive; N % 4 == 0 here)
    for (long long t = (n4 << 2) + (long long)blockIdx.x * 1024 + threadIdx.x;
         t < n; t += stride) {
        atomicAdd(&s_acc[ids[t]], __float2uint_rn(fmaf(losses[t], LSCALE, LBIAS)));
    }
    __syncthreads();

    // flush block partials to global (repacked to 64-bit layout)
    #pragma unroll
    for (int k = threadIdx.x; k < NPROP; k += 1024) {
        unsigned int v = s_acc[k];
        if (v) {
            unsigned long long g =
                ((unsigned long long)(v >> LCNT_SHIFT) << GCNT_SHIFT)
                + (unsigned long long)(v & 0x00FFFFFFu);
            atomicAdd(&g_acc[k], g);
        }
    }
}

// --- Kernel 2: PDL epilogue, 8 blocks x 512 threads, 1 prop/thread -----------
__global__ void __launch_bounds__(512, 1)
epilogue_kernel(const float* __restrict__ prop_freq,
                const int* __restrict__ bc_ptr,
                float* __restrict__ out,
                float n_tokens)
{
    const int k = blockIdx.x * 512 + threadIdx.x;   // 0..4095

    // ---- prefetch everything independent of segacc (overlaps mainloop) ----
    const float pf = __ldg(&prop_freq[k]);
    const float bc = (float)__ldg(bc_ptr);

    const float EMA_DECAY = 0.99f;
    const float ONE_MINUS = 1.0f - 0.99f;
    const float MIN_FREQ  = 1e-5f;
    const float MAX_W     = 30.0f;
    const float WARMUP    = 1000.0f;
    const float SLOW      = 3000.0f;
    const float RAMPB     = 200.0f;

    const float ramp = fminf(1.0f, (bc - WARMUP) / RAMPB);
    const float frac = bc / SLOW;
    const bool  slow_blend = (bc <= SLOW);
    const bool  in_warmup  = (bc <= WARMUP);

    // ---- park until segacc's grid completes and its memory is visible -----
    cudaGridDependencySynchronize();

    unsigned long long v = g_acc[k];
    g_acc[k] = 0ULL;                                // reset scratch for next replay

    float cnt = (float)(v >> GCNT_SHIFT);
    unsigned long long units = v & (GONE - 1ULL);
    float sum = (float)units * GINV_SCALE;
    bool present = cnt > 0.0f;

    float mean = present ? (sum / fmaxf(cnt, 1.0f)) : 0.0f;

    // EMA frequency update
    float bfreq = cnt / (n_tokens + 1e-6f);
    float nf = pf * EMA_DECAY + (present ? ONE_MINUS * bfreq : 0.0f);
    out[2 + k] = nf;

    // inverse-frequency weight with warmup/ramp branches
    float fc  = fmaxf(nf, MIN_FREQ);
    float raw = rsqrtf(fc + 1e-6f);                 // 1/f^0.5
    raw = 1.0f + ramp * (raw - 1.0f);
    raw = fminf(MAX_W, raw);
    if (slow_blend) raw = raw * frac + (1.0f - frac);
    if (in_warmup)  raw = 1.0f;

    float w  = present ? raw : 0.0f;
    float mw = mean * w;

    // block tree reduction (512 threads = 16 warps), fixed order = deterministic
    const unsigned FULL = 0xFFFFFFFFu;
    unsigned long long tu = units;
    #pragma unroll
    for (int off = 16; off > 0; off >>= 1) {
        mw += __shfl_down_sync(FULL, mw, off);
        w  += __shfl_down_sync(FULL, w,  off);
        tu += __shfl_down_sync(FULL, tu, off);
    }
    __shared__ float s_mw[16], s_w[16];
    __shared__ unsigned long long s_tu[16];
    int lane = threadIdx.x & 31, warp = threadIdx.x >> 5;
    if (lane == 0) { s_mw[warp] = mw; s_w[warp] = w; s_tu[warp] = tu; }
    __syncthreads();
    if (threadIdx.x == 0) {
        float bmw = 0.0f, bw = 0.0f;
        unsigned long long btu = 0ULL;
        #pragma unroll
        for (int j = 0; j < 16; j++) { bmw += s_mw[j]; bw += s_w[j]; btu += s_tu[j]; }
        // integer fixed-point atomics: exact + order-independent = deterministic
        atomicAdd(&g_scal[0], (unsigned long long)llrint((double)bmw * SCALE32));
        atomicAdd(&g_scal[1], (unsigned long long)llrint((double)bw  * SCALE32));
        atomicAdd(&g_scal[2], btu);
        __threadfence();
        if (atomicAdd(&g_ticket, 1u) == (unsigned)(gridDim.x - 1)) {
            __threadfence();   // acquire all blocks' g_scal contributions
            double dmw = (double)g_scal[0] / SCALE32;
            double dw  = (double)g_scal[1] / SCALE32;
            double dt  = (double)g_scal[2] * (1.0 / 65536.0);
            out[0] = (float)(dmw / (dw + 1e-6));        // stratified loss
            out[1] = (float)(dt / (double)n_tokens);    // unweighted mean loss
            g_scal[0] = 0ULL; g_scal[1] = 0ULL; g_scal[2] = 0ULL;
            g_ticket = 0;                               // reset for next replay
        }
    }
}

// ---------------------------------------------------------------------------
extern "C" void kernel_launch(void* const* d_in, const int* in_sizes, int n_in,
                              void* d_out, int out_size)
{
    const int*   ids    = (const int*)d_in[0];
    const float* losses = (const float*)d_in[1];
    const float* freq   = (const float*)d_in[2];
    const int*   bc     = (const int*)d_in[3];
    long long n = (long long)in_sizes[0];
    float* out = (float*)d_out;

    segacc_kernel<<<NBLOCKS, 1024>>>(ids, losses, n);

    // PDL epilogue: with the trigger at worker entry, these 8 blocks launch
    // immediately into the free CTA slot per SM, prefetch, and park in
    // GridDependencySynchronize until segacc fully completes.
    cudaLaunchConfig_t cfg = {};
    cfg.gridDim  = dim3(NPROP / 512);
    cfg.blockDim = dim3(512);
    cfg.dynamicSmemBytes = 0;
    cfg.stream = 0;
    cudaLaunchAttribute attrs[1];
    attrs[0].id = cudaLaunchAttributeProgrammaticStreamSerialization;
    attrs[0].val.programmaticStreamSerializationAllowed = 1;
    cfg.attrs = attrs;
    cfg.numAttrs = 1;
    cudaLaunchKernelEx(&cfg, epilogue_kernel, freq, bc, out, (float)n);
}